// round 16
// baseline (speedup 1.0000x reference)
#include <cuda_runtime.h>
#include <cuda_bf16.h>
#include <cuda_fp16.h>
#include <math.h>
#include <stdint.h>

// Problem constants
#define BATCH 4
#define LSEQ 4096
#define DDIM 256
#define NTOK (BATCH * LSEQ)   // 16384
#define L2SEQ (2 * LSEQ)      // 8192 concatenated rows per batch
#define INV_TAU 2.0f
// sqrt(2 / ln 2): fp8 pre-scale so f16 acc = log2(exp(dot/tau))
#define ALPHA 1.69864416f

// fused projection tiling
#define GBK 64
#define GPAD 72
#define PF_STAGE 18432                      // 128 x 72 halves x 2B
#define PF_X 0                              // X stages: 2 x 18432
#define PF_W (2 * PF_STAGE)                 // W1 stages: 2 x 18432 (reused for W2 fp8)
#define PF_H (4 * PF_STAGE)                 // H fp8: 2 stages x 16384
#define PF_SMEM_TOTAL (4 * PF_STAGE + 32768)  // 106496

// fp8 Gram tiling: CTA 128x128, whole K=256 single-stage (A 32KB + B 32KB)
#define Q_A_BYTES (128 * 256)              // 32768
#define Q_B_OFF Q_A_BYTES
#define Q_SMEM_TOTAL (2 * Q_A_BYTES)       // 65536
#define NTILE 64                           // 8192/128 tile rows per batch
#define NTRI (NTILE * (NTILE + 1) / 2)     // 2080 triangular tiles

// ---------------- scratch (device globals; no allocation allowed) -----------
__device__ __half g_X1h[NTOK * DDIM];
__device__ __half g_X2h[NTOK * DDIM];
__device__ __half g_W1h[DDIM * DDIM];
__device__ uint8_t g_W2q[DDIM * DDIM];                   // 16*W2 in e4m3
__device__ __half g_Zb1[NTOK * DDIM];                    // unnormalized Z (f16)
__device__ __half g_Zb2[NTOK * DDIM];
__device__ uint8_t g_Zq[(size_t)BATCH * L2SEQ * DDIM];   // concat [Z1;Z2]*ALPHA fp8
__device__ float g_Rall[BATCH * L2SEQ];                  // rowsums of exp(G/tau)
__device__ float g_D12 [NTOK];
__device__ double g_partial[64];

// ---------------- PTX helpers ------------------------------------------------
__device__ __forceinline__ uint32_t smem_u32(const void* p) {
    uint32_t a;
    asm("{ .reg .u64 t; cvta.to.shared.u64 t, %1; cvt.u32.u64 %0, t; }"
        : "=r"(a) : "l"(p));
    return a;
}

__device__ __forceinline__ void cp_async16(uint32_t s, const void* g) {
    asm volatile("cp.async.cg.shared.global [%0], [%1], 16;" :: "r"(s), "l"(g));
}
__device__ __forceinline__ void cp_commit() {
    asm volatile("cp.async.commit_group;");
}
template <int N>
__device__ __forceinline__ void cp_wait() {
    asm volatile("cp.async.wait_group %0;" :: "n"(N));
}

__device__ __forceinline__ void ldm_x4(uint32_t& r0, uint32_t& r1, uint32_t& r2,
                                       uint32_t& r3, uint32_t addr) {
    asm volatile("ldmatrix.sync.aligned.m8n8.x4.shared.b16 {%0,%1,%2,%3}, [%4];"
                 : "=r"(r0), "=r"(r1), "=r"(r2), "=r"(r3) : "r"(addr));
}

// f16 mma with f16 accumulators (2 acc regs)
__device__ __forceinline__ void mma_f16h(uint32_t* d, const uint32_t* a,
                                         const uint32_t* b) {
    asm volatile(
        "mma.sync.aligned.m16n8k16.row.col.f16.f16.f16.f16 "
        "{%0,%1}, {%2,%3,%4,%5}, {%6,%7}, {%0,%1};"
        : "+r"(d[0]), "+r"(d[1])
        : "r"(a[0]), "r"(a[1]), "r"(a[2]), "r"(a[3]), "r"(b[0]), "r"(b[1]));
}

// FP8 mma with f16 accumulators
__device__ __forceinline__ void mma_e4m3_h(uint32_t* d, const uint32_t* a,
                                           const uint32_t* b) {
    asm volatile(
        "mma.sync.aligned.m16n8k32.row.col.f16.e4m3.e4m3.f16 "
        "{%0,%1}, {%2,%3,%4,%5}, {%6,%7}, {%0,%1};"
        : "+r"(d[0]), "+r"(d[1])
        : "r"(a[0]), "r"(a[1]), "r"(a[2]), "r"(a[3]), "r"(b[0]), "r"(b[1]));
}

__device__ __forceinline__ uint16_t f2_e4m3x2(float lo, float hi) {
    uint16_t r;
    asm("cvt.rn.satfinite.e4m3x2.f32 %0, %1, %2;" : "=h"(r) : "f"(hi), "f"(lo));
    return r;
}

// packed 2^x on f16x2
__device__ __forceinline__ uint32_t ex2_h2(uint32_t x) {
    uint32_t r;
    asm("ex2.approx.f16x2 %0, %1;" : "=r"(r) : "r"(x));
    return r;
}

__device__ __forceinline__ uint32_t hadd2u(uint32_t a, uint32_t b) {
    uint32_t r;
    asm("add.f16x2 %0, %1, %2;" : "=r"(r) : "r"(a), "r"(b));
    return r;
}

// ---------------- fused converts -----------------------------------------------
#define NX4 (NTOK * DDIM / 4)     // 1048576
#define NW4 (DDIM * DDIM / 4)     // 16384
#define CVT_TOTAL (2 * NX4 + 2 * NW4)

__global__ void cvt_all_kernel(const float* __restrict__ X1,
                               const float* __restrict__ X2,
                               const float* __restrict__ W1,
                               const float* __restrict__ W2) {
    int i = blockIdx.x * blockDim.x + threadIdx.x;
    if (i >= CVT_TOTAL) return;
    if (i < 2 * NX4 + NW4) {
        const float* src;
        __half* dst;
        int k;
        if (i < NX4)          { src = X1; dst = g_X1h; k = i; }
        else if (i < 2 * NX4) { src = X2; dst = g_X2h; k = i - NX4; }
        else                  { src = W1; dst = g_W1h; k = i - 2 * NX4; }
        float4 v = reinterpret_cast<const float4*>(src)[k];
        __half2* d = reinterpret_cast<__half2*>(dst) + k * 2;
        d[0] = __floats2half2_rn(v.x, v.y);
        d[1] = __floats2half2_rn(v.z, v.w);
    } else {
        int k = i - 2 * NX4 - NW4;
        float4 v = reinterpret_cast<const float4*>(W2)[k];
        uint32_t q = (uint32_t)f2_e4m3x2(16.f * v.x, 16.f * v.y)
                   | ((uint32_t)f2_e4m3x2(16.f * v.z, 16.f * v.w) << 16);
        reinterpret_cast<uint32_t*>(g_W2q)[k] = q;
    }
}

// ---------------- fused projection: Zb = (ELU(X W1^T + b1)) W2^T + b2 --------
__global__ __launch_bounds__(256, 2)
void proj_fused(const float* __restrict__ b1, const float* __restrict__ b2) {
    extern __shared__ __align__(128) char smem[];
    const uint32_t sbase = smem_u32(smem);

    const int tid  = threadIdx.x;
    const int wid  = tid >> 5;
    const int lane = tid & 31;
    const int z    = blockIdx.y;
    const int bm   = blockIdx.x * 128;

    const __half* Xbase = (z ? g_X2h : g_X1h) + (size_t)bm * DDIM;
    __half* Zb = z ? g_Zb2 : g_Zb1;

    const int wm = (wid & 3) * 32;
    const int wn = (wid >> 2) * 64;

    // ========== GEMM1: H = ELU(X @ W1^T + b1), two 128-col passes ==========
#pragma unroll 1
    for (int nt = 0; nt < 2; nt++) {
        const __half* Bbase = g_W1h + (size_t)(nt * 128) * DDIM;

        uint32_t acc[2][8][2];
#pragma unroll
        for (int mi = 0; mi < 2; mi++)
#pragma unroll
            for (int nj = 0; nj < 8; nj++) { acc[mi][nj][0] = 0u; acc[mi][nj][1] = 0u; }

        auto load_stage = [&](int buf, int kt) {
            const int kofs = kt * GBK;
#pragma unroll
            for (int it = 0; it < 4; it++) {
                int idx = tid + it * 256;
                int row = idx >> 3;
                int ch  = idx & 7;
                cp_async16(sbase + PF_X + buf * PF_STAGE + row * (GPAD * 2) + ch * 16,
                           Xbase + (size_t)row * DDIM + kofs + ch * 8);
                cp_async16(sbase + PF_W + buf * PF_STAGE + row * (GPAD * 2) + ch * 16,
                           Bbase + (size_t)row * DDIM + kofs + ch * 8);
            }
        };

        load_stage(0, 0);
        cp_commit();

        int buf = 0;
#pragma unroll
        for (int kt = 0; kt < DDIM / GBK; kt++) {
            if (kt + 1 < DDIM / GBK) {
                load_stage(buf ^ 1, kt + 1);
                cp_commit();
                cp_wait<1>();
            } else {
                cp_wait<0>();
            }
            __syncthreads();

            const uint32_t aBuf = sbase + PF_X + buf * PF_STAGE;
            const uint32_t bBuf = sbase + PF_W + buf * PF_STAGE;

#pragma unroll
            for (int ks = 0; ks < GBK / 16; ks++) {
                uint32_t afr[2][4];
#pragma unroll
                for (int mi = 0; mi < 2; mi++) {
                    int r = wm + mi * 16 + (lane & 15);
                    int c = ks * 16 + (lane >> 4) * 8;
                    ldm_x4(afr[mi][0], afr[mi][1], afr[mi][2], afr[mi][3],
                           aBuf + r * (GPAD * 2) + c * 2);
                }
                uint32_t bfr[4][4];
#pragma unroll
                for (int bi = 0; bi < 4; bi++) {
                    int r = wn + bi * 16 + (lane & 7) + ((lane >> 4) << 3);
                    int c = ks * 16 + ((lane >> 3) & 1) * 8;
                    ldm_x4(bfr[bi][0], bfr[bi][1], bfr[bi][2], bfr[bi][3],
                           bBuf + r * (GPAD * 2) + c * 2);
                }
#pragma unroll
                for (int mi = 0; mi < 2; mi++)
#pragma unroll
                    for (int bi = 0; bi < 4; bi++) {
                        mma_f16h(acc[mi][bi * 2 + 0], afr[mi], &bfr[bi][0]);
                        mma_f16h(acc[mi][bi * 2 + 1], afr[mi], &bfr[bi][2]);
                    }
            }
            __syncthreads();
            buf ^= 1;
        }

        // epilogue: bias + ELU -> e4m3 -> H smem (swizzled, stage = nt)
#pragma unroll
        for (int mi = 0; mi < 2; mi++)
#pragma unroll
            for (int nj = 0; nj < 8; nj++) {
                int c = wn + nj * 8 + (lane & 3) * 2;     // 0..126, even
                int colg = nt * 128 + c;
                float bb0 = __ldg(&b1[colg]);
                float bb1 = __ldg(&b1[colg + 1]);
                int r0 = wm + mi * 16 + (lane >> 2);      // local row
                float2 p0 = __half22float2(*reinterpret_cast<const __half2*>(&acc[mi][nj][0]));
                float2 p1 = __half22float2(*reinterpret_cast<const __half2*>(&acc[mi][nj][1]));
                float v00 = p0.x + bb0, v01 = p0.y + bb1;
                float v10 = p1.x + bb0, v11 = p1.y + bb1;
                v00 = v00 > 0.f ? v00 : expm1f(v00);
                v01 = v01 > 0.f ? v01 : expm1f(v01);
                v10 = v10 > 0.f ? v10 : expm1f(v10);
                v11 = v11 > 0.f ? v11 : expm1f(v11);
                uint16_t h0 = f2_e4m3x2(v00, v01);
                uint16_t h1 = f2_e4m3x2(v10, v11);
                int ch = c >> 4, off = c & 15;
                int sw = (ch ^ (r0 & 7)) * 16 + off;      // (r0+8)&7 == r0&7
                *reinterpret_cast<uint16_t*>(smem + PF_H + nt * 16384 + r0 * 128 + sw) = h0;
                *reinterpret_cast<uint16_t*>(smem + PF_H + nt * 16384 + (r0 + 8) * 128 + sw) = h1;
            }
        __syncthreads();   // H(nt) visible; sX/sW reusable
    }

    // ========== GEMM2: Zb = (H @ (16 W2)^T)/16 + b2, two 128-col passes =====
#pragma unroll 1
    for (int nt2 = 0; nt2 < 2; nt2++) {
        __syncthreads();   // sW free (prev readers done)
        const uint8_t* W2base = g_W2q + (size_t)(nt2 * 128) * DDIM;
#pragma unroll
        for (int s = 0; s < 2; s++) {
#pragma unroll
            for (int it = 0; it < 4; it++) {
                int idx = tid + it * 256;       // 0..1023
                int row = idx >> 3;             // 0..127
                int ch  = idx & 7;
                uint32_t sw = (uint32_t)((ch ^ (row & 7)) * 16);
                cp_async16(sbase + PF_W + s * 16384 + row * 128 + sw,
                           W2base + (size_t)row * DDIM + s * 128 + ch * 16);
            }
        }
        cp_commit();
        cp_wait<0>();
        __syncthreads();

        uint32_t acc[2][8][2];
#pragma unroll
        for (int mi = 0; mi < 2; mi++)
#pragma unroll
            for (int nj = 0; nj < 8; nj++) { acc[mi][nj][0] = 0u; acc[mi][nj][1] = 0u; }

#pragma unroll
        for (int s = 0; s < 2; s++) {
            const uint32_t aS = sbase + PF_H + s * 16384;
            const uint32_t bS = sbase + PF_W + s * 16384;
#pragma unroll
            for (int ks = 0; ks < 4; ks++) {
                uint32_t afr[2][4];
#pragma unroll
                for (int mi = 0; mi < 2; mi++) {
                    int r = wm + mi * 16 + (lane & 15);
                    int c16 = ks * 2 + (lane >> 4);
                    ldm_x4(afr[mi][0], afr[mi][1], afr[mi][2], afr[mi][3],
                           aS + r * 128 + ((c16 ^ (r & 7)) * 16));
                }
                uint32_t bfr[4][4];
#pragma unroll
                for (int bi = 0; bi < 4; bi++) {
                    int r = wn + bi * 16 + (lane & 7) + ((lane >> 4) << 3);
                    int c16 = ks * 2 + ((lane >> 3) & 1);
                    ldm_x4(bfr[bi][0], bfr[bi][1], bfr[bi][2], bfr[bi][3],
                           bS + r * 128 + ((c16 ^ (r & 7)) * 16));
                }
#pragma unroll
                for (int mi = 0; mi < 2; mi++)
#pragma unroll
                    for (int bi = 0; bi < 4; bi++) {
                        mma_e4m3_h(acc[mi][bi * 2 + 0], afr[mi], &bfr[bi][0]);
                        mma_e4m3_h(acc[mi][bi * 2 + 1], afr[mi], &bfr[bi][2]);
                    }
            }
        }

        // epilogue: /16 + bias -> Zb (f16, gmem)
#pragma unroll
        for (int mi = 0; mi < 2; mi++)
#pragma unroll
            for (int nj = 0; nj < 8; nj++) {
                int col = nt2 * 128 + wn + nj * 8 + (lane & 3) * 2;
                float bb0 = __ldg(&b2[col]);
                float bb1 = __ldg(&b2[col + 1]);
                int r0 = bm + wm + mi * 16 + (lane >> 2);
                float2 p0 = __half22float2(*reinterpret_cast<const __half2*>(&acc[mi][nj][0]));
                float2 p1 = __half22float2(*reinterpret_cast<const __half2*>(&acc[mi][nj][1]));
                *reinterpret_cast<__half2*>(Zb + (size_t)r0 * DDIM + col)
                    = __floats2half2_rn(p0.x * 0.0625f + bb0, p0.y * 0.0625f + bb1);
                *reinterpret_cast<__half2*>(Zb + (size_t)(r0 + 8) * DDIM + col)
                    = __floats2half2_rn(p1.x * 0.0625f + bb0, p1.y * 0.0625f + bb1);
            }
    }
}

// ---------------- normalize (from f16) + scaled fp8 concat + diag ------------
__global__ void normdiag_kernel() {
    int n    = blockIdx.x * 8 + (threadIdx.x >> 5);
    int lane = threadIdx.x & 31;
    int b = n >> 12, r = n & 4095;

    uint4 u1 = reinterpret_cast<const uint4*>(g_Zb1 + (size_t)n * DDIM)[lane];
    uint4 u2 = reinterpret_cast<const uint4*>(g_Zb2 + (size_t)n * DDIM)[lane];

    float a[8], c[8];
    {
        float2 t;
        t = __half22float2(*(const __half2*)&u1.x); a[0]=t.x; a[1]=t.y;
        t = __half22float2(*(const __half2*)&u1.y); a[2]=t.x; a[3]=t.y;
        t = __half22float2(*(const __half2*)&u1.z); a[4]=t.x; a[5]=t.y;
        t = __half22float2(*(const __half2*)&u1.w); a[6]=t.x; a[7]=t.y;
        t = __half22float2(*(const __half2*)&u2.x); c[0]=t.x; c[1]=t.y;
        t = __half22float2(*(const __half2*)&u2.y); c[2]=t.x; c[3]=t.y;
        t = __half22float2(*(const __half2*)&u2.z); c[4]=t.x; c[5]=t.y;
        t = __half22float2(*(const __half2*)&u2.w); c[6]=t.x; c[7]=t.y;
    }

    float s1 = 0.f, s2 = 0.f, d = 0.f;
#pragma unroll
    for (int i = 0; i < 8; i++) {
        s1 += a[i] * a[i];
        s2 += c[i] * c[i];
        d  += a[i] * c[i];
    }
#pragma unroll
    for (int off = 16; off >= 1; off >>= 1) {
        s1 += __shfl_xor_sync(0xffffffffu, s1, off);
        s2 += __shfl_xor_sync(0xffffffffu, s2, off);
        d  += __shfl_xor_sync(0xffffffffu, d, off);
    }
    float i1 = ALPHA / fmaxf(sqrtf(s1), 1e-12f);   // fold ALPHA into fp8 values
    float i2 = ALPHA / fmaxf(sqrtf(s2), 1e-12f);

    uint2 q1, q2;
    q1.x = (uint32_t)f2_e4m3x2(a[0]*i1, a[1]*i1) | ((uint32_t)f2_e4m3x2(a[2]*i1, a[3]*i1) << 16);
    q1.y = (uint32_t)f2_e4m3x2(a[4]*i1, a[5]*i1) | ((uint32_t)f2_e4m3x2(a[6]*i1, a[7]*i1) << 16);
    q2.x = (uint32_t)f2_e4m3x2(c[0]*i2, c[1]*i2) | ((uint32_t)f2_e4m3x2(c[2]*i2, c[3]*i2) << 16);
    q2.y = (uint32_t)f2_e4m3x2(c[4]*i2, c[5]*i2) | ((uint32_t)f2_e4m3x2(c[6]*i2, c[7]*i2) << 16);
    reinterpret_cast<uint2*>(g_Zq + ((size_t)b * L2SEQ + r) * DDIM)[lane] = q1;
    reinterpret_cast<uint2*>(g_Zq + ((size_t)b * L2SEQ + LSEQ + r) * DDIM)[lane] = q2;

    if (lane == 0) {
        float nn = fmaxf(sqrtf(s1), 1e-12f) * fmaxf(sqrtf(s2), 1e-12f);
        g_D12[n] = __expf(d / nn * INV_TAU);
        g_Rall[b * L2SEQ + r] = 0.f;
        g_Rall[b * L2SEQ + LSEQ + r] = 0.f;
    }
}

// ---------------- FP8 symmetric Gram (single-stage full-K, occ 3) ------------
__global__ __launch_bounds__(256, 3)
void gram_fp8() {
    // decode triangular tile index
    int t = blockIdx.x;
    int i = (int)((2 * NTILE + 1 -
                   sqrtf((float)((2 * NTILE + 1) * (2 * NTILE + 1) - 8 * t))) * 0.5f);
    while ((i + 1) * NTILE - ((i + 1) * i) / 2 <= t) i++;
    while (i * NTILE - (i * (i - 1)) / 2 > t) i--;
    int j = i + (t - (i * NTILE - (i * (i - 1)) / 2));
    const bool do_col = (j != i);
    const int b = blockIdx.y;

    extern __shared__ __align__(128) char smem[];
    const uint32_t sbase = smem_u32(smem);
    const uint32_t sA = sbase;
    const uint32_t sB = sbase + Q_B_OFF;

    const int tid  = threadIdx.x;
    const int wid  = tid >> 5;
    const int lane = tid & 31;

    const uint8_t* Abase = g_Zq + ((size_t)b * L2SEQ + i * 128) * DDIM;
    const uint8_t* Bbase = g_Zq + ((size_t)b * L2SEQ + j * 128) * DDIM;

    const int wm = (wid & 3) * 32;
    const int wn = (wid >> 2) * 64;

    // ---- single-stage load: whole 128 x 256B A and B tiles (row = 2 swizzled
    // 128B groups; group g of row holds K bytes [g*128, g*128+128))
#pragma unroll
    for (int it = 0; it < 8; it++) {
        int idx = tid + it * 256;          // 0..2047
        int row = idx >> 4;                // 0..127
        int ch  = idx & 15;                // 16B chunk in the 256B row
        int g   = ch >> 3;                 // which 128B group
        int c8  = ch & 7;
        uint32_t sw = (uint32_t)(g * 128 + ((c8 ^ (row & 7)) * 16));
        cp_async16(sA + row * 256 + sw, Abase + (size_t)row * DDIM + ch * 16);
        cp_async16(sB + row * 256 + sw, Bbase + (size_t)row * DDIM + ch * 16);
    }
    cp_commit();

    uint32_t acc[2][8][2];
#pragma unroll
    for (int mi = 0; mi < 2; mi++)
#pragma unroll
        for (int nj = 0; nj < 8; nj++) { acc[mi][nj][0] = 0u; acc[mi][nj][1] = 0u; }

    cp_wait<0>();
    __syncthreads();

#pragma unroll
    for (int ks = 0; ks < 8; ks++) {       // K=32 bytes each; g = ks>>2
        const int g = ks >> 2;
        const int kk = ks & 3;
        uint32_t afr[2][4];
#pragma unroll
        for (int mi = 0; mi < 2; mi++) {
            int r = wm + mi * 16 + (lane & 15);
            int c16 = kk * 2 + (lane >> 4);
            ldm_x4(afr[mi][0], afr[mi][1], afr[mi][2], afr[mi][3],
                   sA + r * 256 + g * 128 + ((c16 ^ (r & 7)) * 16));
        }
        uint32_t bfr[4][4];
#pragma unroll
        for (int bi = 0; bi < 4; bi++) {
            int r = wn + bi * 16 + (lane & 7) + ((lane >> 4) << 3);
            int c16 = kk * 2 + ((lane >> 3) & 1);
            ldm_x4(bfr[bi][0], bfr[bi][1], bfr[bi][2], bfr[bi][3],
                   sB + r * 256 + g * 128 + ((c16 ^ (r & 7)) * 16));
        }
#pragma unroll
        for (int mi = 0; mi < 2; mi++)
#pragma unroll
            for (int bi = 0; bi < 4; bi++) {
                mma_e4m3_h(acc[mi][bi * 2 + 0], afr[mi], &bfr[bi][0]);
                mma_e4m3_h(acc[mi][bi * 2 + 1], afr[mi], &bfr[bi][2]);
            }
    }

    // ---- epilogue: packed 2^x; rs AND cs fully packed half2
    float* Rb = g_Rall + b * L2SEQ;
    const int bm = i * 128, bn = j * 128;

    uint32_t rsh0[2] = {0u, 0u};   // [mi]: row r, packed (col c, c+1) partials
    uint32_t rsh1[2] = {0u, 0u};   // [mi]: row r+8
    uint32_t csh[8];
#pragma unroll
    for (int nj = 0; nj < 8; nj++) csh[nj] = 0u;

#pragma unroll
    for (int mi = 0; mi < 2; mi++)
#pragma unroll
        for (int nj = 0; nj < 8; nj++) {
            uint32_t e0 = ex2_h2(acc[mi][nj][0]);   // (row r,   col c | c+1)
            uint32_t e1 = ex2_h2(acc[mi][nj][1]);   // (row r+8, col c | c+1)
            rsh0[mi] = hadd2u(rsh0[mi], e0);
            rsh1[mi] = hadd2u(rsh1[mi], e1);
            csh[nj] = hadd2u(csh[nj], hadd2u(e0, e1));
        }

    // row reduce across the 4 lanes sharing a row (lane bits 0-1), packed
#pragma unroll
    for (int off = 1; off <= 2; off <<= 1)
#pragma unroll
        for (int mi = 0; mi < 2; mi++) {
            rsh0[mi] = hadd2u(rsh0[mi], __shfl_xor_sync(0xffffffffu, rsh0[mi], off));
            rsh1[mi] = hadd2u(rsh1[mi], __shfl_xor_sync(0xffffffffu, rsh1[mi], off));
        }
    if ((lane & 3) == 0) {
#pragma unroll
        for (int mi = 0; mi < 2; mi++) {
            int row = bm + wm + mi * 16 + (lane >> 2);
            float2 v0 = __half22float2(*reinterpret_cast<const __half2*>(&rsh0[mi]));
            float2 v1 = __half22float2(*reinterpret_cast<const __half2*>(&rsh1[mi]));
            atomicAdd(&Rb[row], v0.x + v0.y);
            atomicAdd(&Rb[row + 8], v1.x + v1.y);
        }
    }

    if (do_col) {
#pragma unroll
        for (int off = 4; off <= 16; off <<= 1)
#pragma unroll
            for (int nj = 0; nj < 8; nj++)
                csh[nj] = hadd2u(csh[nj], __shfl_xor_sync(0xffffffffu, csh[nj], off));
        if (lane < 4) {
#pragma unroll
            for (int nj = 0; nj < 8; nj++) {
                float2 cv = __half22float2(*reinterpret_cast<const __half2*>(&csh[nj]));
                int col = bn + wn + nj * 8 + lane * 2;
                atomicAdd(&Rb[col], cv.x);
                atomicAdd(&Rb[col + 1], cv.y);
            }
        }
    }
}

// ---------------- final scalar reduction (2 stages) ---------------------------
__global__ void final1_kernel() {
    __shared__ double sred[256];
    const float E2 = 7.3890560989306495f;   // exp(||z||^2 / tau) = exp(2)
    int n = blockIdx.x * 256 + threadIdx.x;  // 64 blocks x 256 = 16384
    int b = n >> 12, r = n & 4095;
    float d1 = g_Rall[b * L2SEQ + r] - E2;
    float d2 = g_Rall[b * L2SEQ + LSEQ + r] - E2;
    double acc = (double)(logf(d1) + logf(d2) - 2.f * logf(g_D12[n]));
    sred[threadIdx.x] = acc;
    __syncthreads();
    for (int s = 128; s > 0; s >>= 1) {
        if (threadIdx.x < s) sred[threadIdx.x] += sred[threadIdx.x + s];
        __syncthreads();
    }
    if (threadIdx.x == 0) g_partial[blockIdx.x] = sred[0];
}

__global__ void final2_kernel(float* __restrict__ out) {
    __shared__ double sred[64];
    sred[threadIdx.x] = g_partial[threadIdx.x];
    __syncthreads();
    for (int s = 32; s > 0; s >>= 1) {
        if (threadIdx.x < s) sred[threadIdx.x] += sred[threadIdx.x + s];
        __syncthreads();
    }
    if (threadIdx.x == 0) out[0] = (float)(sred[0] / (2.0 * BATCH));
}

// ---------------- launch -------------------------------------------------------
extern "C" void kernel_launch(void* const* d_in, const int* in_sizes, int n_in,
                              void* d_out, int out_size) {
    (void)in_sizes; (void)n_in; (void)out_size;
    const float* X1 = (const float*)d_in[0];
    const float* X2 = (const float*)d_in[1];
    const float* W1 = (const float*)d_in[2];
    const float* b1 = (const float*)d_in[3];
    const float* W2 = (const float*)d_in[4];
    const float* b2 = (const float*)d_in[5];
    float* out = (float*)d_out;

    cudaFuncSetAttribute(proj_fused, cudaFuncAttributeMaxDynamicSharedMemorySize, PF_SMEM_TOTAL);
    cudaFuncSetAttribute(gram_fp8, cudaFuncAttributeMaxDynamicSharedMemorySize, Q_SMEM_TOTAL);

    cvt_all_kernel<<<(CVT_TOTAL + 255) / 256, 256>>>(X1, X2, W1, W2);  // launch 0

    proj_fused<<<dim3(NTOK / 128, 2), 256, PF_SMEM_TOTAL>>>(b1, b2);   // launch 1

    normdiag_kernel<<<NTOK / 8, 256>>>();                              // launch 2

    gram_fp8<<<dim3(NTRI, BATCH), 256, Q_SMEM_TOTAL>>>();              // launch 3

    final1_kernel<<<64, 256>>>();                                      // launch 4
    final2_kernel<<<1, 64>>>(out);                                     // launch 5
}

// round 17
// speedup vs baseline: 1.0178x; 1.0178x over previous
#include <cuda_runtime.h>
#include <cuda_bf16.h>
#include <cuda_fp16.h>
#include <math.h>
#include <stdint.h>

// Problem constants
#define BATCH 4
#define LSEQ 4096
#define DDIM 256
#define NTOK (BATCH * LSEQ)   // 16384
#define L2SEQ (2 * LSEQ)      // 8192 concatenated rows per batch
#define INV_TAU 2.0f
// sqrt(2 / ln 2): fp8 pre-scale so f16 acc = log2(exp(dot/tau))
#define ALPHA 1.69864416f

// fused projection tiling
#define GBK 64
#define GPAD 72
#define PF_STAGE 18432                      // 128 x 72 halves x 2B
#define PF_X 0                              // X stages: 2 x 18432 (W2 tile 1 later)
#define PF_W (2 * PF_STAGE)                 // W1 stages: 2 x 18432 (W2 tile 0 later)
#define PF_H (4 * PF_STAGE)                 // H fp8: 2 halves x 16384
#define PF_SMEM_TOTAL (4 * PF_STAGE + 32768)  // 106496

// fp8 Gram tiling: CTA 128x128, K=256 in two 128B stages, SW swizzle
#define QSTAGE_BYTES (128 * 128)           // 16384 per stage
#define Q_B_OFF (2 * QSTAGE_BYTES)
#define Q_SMEM_TOTAL (4 * QSTAGE_BYTES)    // 65536
#define NTILE 64                           // 8192/128 tile rows per batch
#define NTRI (NTILE * (NTILE + 1) / 2)     // 2080 triangular tiles

// ---------------- scratch (device globals; no allocation allowed) -----------
__device__ __half g_X1h[NTOK * DDIM];
__device__ __half g_X2h[NTOK * DDIM];
__device__ __half g_W1h[DDIM * DDIM];
__device__ uint8_t g_W2q[DDIM * DDIM];                   // 16*W2 in e4m3
__device__ __half g_Zb1[NTOK * DDIM];                    // unnormalized Z (f16)
__device__ __half g_Zb2[NTOK * DDIM];
__device__ uint8_t g_Zq[(size_t)BATCH * L2SEQ * DDIM];   // concat [Z1;Z2]*ALPHA fp8
__device__ float g_Rall[BATCH * L2SEQ];                  // rowsums of exp(G/tau)
__device__ float g_D12 [NTOK];
__device__ double g_partial[64];

// ---------------- PTX helpers ------------------------------------------------
__device__ __forceinline__ uint32_t smem_u32(const void* p) {
    uint32_t a;
    asm("{ .reg .u64 t; cvta.to.shared.u64 t, %1; cvt.u32.u64 %0, t; }"
        : "=r"(a) : "l"(p));
    return a;
}

__device__ __forceinline__ void cp_async16(uint32_t s, const void* g) {
    asm volatile("cp.async.cg.shared.global [%0], [%1], 16;" :: "r"(s), "l"(g));
}
__device__ __forceinline__ void cp_commit() {
    asm volatile("cp.async.commit_group;");
}
template <int N>
__device__ __forceinline__ void cp_wait() {
    asm volatile("cp.async.wait_group %0;" :: "n"(N));
}

__device__ __forceinline__ void ldm_x4(uint32_t& r0, uint32_t& r1, uint32_t& r2,
                                       uint32_t& r3, uint32_t addr) {
    asm volatile("ldmatrix.sync.aligned.m8n8.x4.shared.b16 {%0,%1,%2,%3}, [%4];"
                 : "=r"(r0), "=r"(r1), "=r"(r2), "=r"(r3) : "r"(addr));
}

// f16 mma with f16 accumulators (2 acc regs)
__device__ __forceinline__ void mma_f16h(uint32_t* d, const uint32_t* a,
                                         const uint32_t* b) {
    asm volatile(
        "mma.sync.aligned.m16n8k16.row.col.f16.f16.f16.f16 "
        "{%0,%1}, {%2,%3,%4,%5}, {%6,%7}, {%0,%1};"
        : "+r"(d[0]), "+r"(d[1])
        : "r"(a[0]), "r"(a[1]), "r"(a[2]), "r"(a[3]), "r"(b[0]), "r"(b[1]));
}

// FP8 mma with f16 accumulators
__device__ __forceinline__ void mma_e4m3_h(uint32_t* d, const uint32_t* a,
                                           const uint32_t* b) {
    asm volatile(
        "mma.sync.aligned.m16n8k32.row.col.f16.e4m3.e4m3.f16 "
        "{%0,%1}, {%2,%3,%4,%5}, {%6,%7}, {%0,%1};"
        : "+r"(d[0]), "+r"(d[1])
        : "r"(a[0]), "r"(a[1]), "r"(a[2]), "r"(a[3]), "r"(b[0]), "r"(b[1]));
}

__device__ __forceinline__ uint16_t f2_e4m3x2(float lo, float hi) {
    uint16_t r;
    asm("cvt.rn.satfinite.e4m3x2.f32 %0, %1, %2;" : "=h"(r) : "f"(hi), "f"(lo));
    return r;
}

// packed 2^x on f16x2
__device__ __forceinline__ uint32_t ex2_h2(uint32_t x) {
    uint32_t r;
    asm("ex2.approx.f16x2 %0, %1;" : "=r"(r) : "r"(x));
    return r;
}

__device__ __forceinline__ uint32_t hadd2u(uint32_t a, uint32_t b) {
    uint32_t r;
    asm("add.f16x2 %0, %1, %2;" : "=r"(r) : "r"(a), "r"(b));
    return r;
}

// ---------------- fused converts -----------------------------------------------
#define NX4 (NTOK * DDIM / 4)     // 1048576
#define NW4 (DDIM * DDIM / 4)     // 16384
#define CVT_TOTAL (2 * NX4 + 2 * NW4)

__global__ void cvt_all_kernel(const float* __restrict__ X1,
                               const float* __restrict__ X2,
                               const float* __restrict__ W1,
                               const float* __restrict__ W2) {
    int i = blockIdx.x * blockDim.x + threadIdx.x;
    if (i >= CVT_TOTAL) return;
    if (i < 2 * NX4 + NW4) {
        const float* src;
        __half* dst;
        int k;
        if (i < NX4)          { src = X1; dst = g_X1h; k = i; }
        else if (i < 2 * NX4) { src = X2; dst = g_X2h; k = i - NX4; }
        else                  { src = W1; dst = g_W1h; k = i - 2 * NX4; }
        float4 v = reinterpret_cast<const float4*>(src)[k];
        __half2* d = reinterpret_cast<__half2*>(dst) + k * 2;
        d[0] = __floats2half2_rn(v.x, v.y);
        d[1] = __floats2half2_rn(v.z, v.w);
    } else {
        int k = i - 2 * NX4 - NW4;
        float4 v = reinterpret_cast<const float4*>(W2)[k];
        uint32_t q = (uint32_t)f2_e4m3x2(16.f * v.x, 16.f * v.y)
                   | ((uint32_t)f2_e4m3x2(16.f * v.z, 16.f * v.w) << 16);
        reinterpret_cast<uint32_t*>(g_W2q)[k] = q;
    }
}

// ---------------- fused projection: Zb = (ELU(X W1^T + b1)) W2^T + b2 --------
// W2 fp8 tiles preloaded during GEMM1's final epilogue; GEMM2 runs both
// 128-col passes back-to-back with a single wait+sync.
__global__ __launch_bounds__(256, 2)
void proj_fused(const float* __restrict__ b1, const float* __restrict__ b2) {
    extern __shared__ __align__(128) char smem[];
    const uint32_t sbase = smem_u32(smem);

    const int tid  = threadIdx.x;
    const int wid  = tid >> 5;
    const int lane = tid & 31;
    const int z    = blockIdx.y;
    const int bm   = blockIdx.x * 128;

    const __half* Xbase = (z ? g_X2h : g_X1h) + (size_t)bm * DDIM;
    __half* Zb = z ? g_Zb2 : g_Zb1;

    const int wm = (wid & 3) * 32;
    const int wn = (wid >> 2) * 64;

    // ========== GEMM1: H = ELU(X @ W1^T + b1), two 128-col passes ==========
#pragma unroll 1
    for (int nt = 0; nt < 2; nt++) {
        const __half* Bbase = g_W1h + (size_t)(nt * 128) * DDIM;

        uint32_t acc[2][8][2];
#pragma unroll
        for (int mi = 0; mi < 2; mi++)
#pragma unroll
            for (int nj = 0; nj < 8; nj++) { acc[mi][nj][0] = 0u; acc[mi][nj][1] = 0u; }

        auto load_stage = [&](int buf, int kt) {
            const int kofs = kt * GBK;
#pragma unroll
            for (int it = 0; it < 4; it++) {
                int idx = tid + it * 256;
                int row = idx >> 3;
                int ch  = idx & 7;
                cp_async16(sbase + PF_X + buf * PF_STAGE + row * (GPAD * 2) + ch * 16,
                           Xbase + (size_t)row * DDIM + kofs + ch * 8);
                cp_async16(sbase + PF_W + buf * PF_STAGE + row * (GPAD * 2) + ch * 16,
                           Bbase + (size_t)row * DDIM + kofs + ch * 8);
            }
        };

        load_stage(0, 0);
        cp_commit();

        int buf = 0;
#pragma unroll
        for (int kt = 0; kt < DDIM / GBK; kt++) {
            if (kt + 1 < DDIM / GBK) {
                load_stage(buf ^ 1, kt + 1);
                cp_commit();
                cp_wait<1>();
            } else {
                cp_wait<0>();
            }
            __syncthreads();

            const uint32_t aBuf = sbase + PF_X + buf * PF_STAGE;
            const uint32_t bBuf = sbase + PF_W + buf * PF_STAGE;

#pragma unroll
            for (int ks = 0; ks < GBK / 16; ks++) {
                uint32_t afr[2][4];
#pragma unroll
                for (int mi = 0; mi < 2; mi++) {
                    int r = wm + mi * 16 + (lane & 15);
                    int c = ks * 16 + (lane >> 4) * 8;
                    ldm_x4(afr[mi][0], afr[mi][1], afr[mi][2], afr[mi][3],
                           aBuf + r * (GPAD * 2) + c * 2);
                }
                uint32_t bfr[4][4];
#pragma unroll
                for (int bi = 0; bi < 4; bi++) {
                    int r = wn + bi * 16 + (lane & 7) + ((lane >> 4) << 3);
                    int c = ks * 16 + ((lane >> 3) & 1) * 8;
                    ldm_x4(bfr[bi][0], bfr[bi][1], bfr[bi][2], bfr[bi][3],
                           bBuf + r * (GPAD * 2) + c * 2);
                }
#pragma unroll
                for (int mi = 0; mi < 2; mi++)
#pragma unroll
                    for (int bi = 0; bi < 4; bi++) {
                        mma_f16h(acc[mi][bi * 2 + 0], afr[mi], &bfr[bi][0]);
                        mma_f16h(acc[mi][bi * 2 + 1], afr[mi], &bfr[bi][2]);
                    }
            }
            __syncthreads();
            buf ^= 1;
        }

        // After nt=1's mainloop, PF_X/PF_W regions are free: start W2 preload
        // (fp8, gram-style layout) so it overlaps the ELU/quantize epilogue.
        if (nt == 1) {
#pragma unroll
            for (int nt2 = 0; nt2 < 2; nt2++) {
                const uint8_t* W2base = g_W2q + (size_t)(nt2 * 128) * DDIM;
                const uint32_t dstreg = sbase + (nt2 ? PF_X : PF_W);
#pragma unroll
                for (int s = 0; s < 2; s++) {
#pragma unroll
                    for (int it = 0; it < 4; it++) {
                        int idx = tid + it * 256;       // 0..1023
                        int row = idx >> 3;             // 0..127
                        int ch  = idx & 7;
                        uint32_t sw = (uint32_t)((ch ^ (row & 7)) * 16);
                        cp_async16(dstreg + s * 16384 + row * 128 + sw,
                                   W2base + (size_t)row * DDIM + s * 128 + ch * 16);
                    }
                }
            }
            cp_commit();
        }

        // epilogue: bias + ELU -> e4m3 -> H smem (swizzled, stage = nt)
#pragma unroll
        for (int mi = 0; mi < 2; mi++)
#pragma unroll
            for (int nj = 0; nj < 8; nj++) {
                int c = wn + nj * 8 + (lane & 3) * 2;     // 0..126, even
                int colg = nt * 128 + c;
                float bb0 = __ldg(&b1[colg]);
                float bb1 = __ldg(&b1[colg + 1]);
                int r0 = wm + mi * 16 + (lane >> 2);      // local row
                float2 p0 = __half22float2(*reinterpret_cast<const __half2*>(&acc[mi][nj][0]));
                float2 p1 = __half22float2(*reinterpret_cast<const __half2*>(&acc[mi][nj][1]));
                float v00 = p0.x + bb0, v01 = p0.y + bb1;
                float v10 = p1.x + bb0, v11 = p1.y + bb1;
                v00 = v00 > 0.f ? v00 : expm1f(v00);
                v01 = v01 > 0.f ? v01 : expm1f(v01);
                v10 = v10 > 0.f ? v10 : expm1f(v10);
                v11 = v11 > 0.f ? v11 : expm1f(v11);
                uint16_t h0 = f2_e4m3x2(v00, v01);
                uint16_t h1 = f2_e4m3x2(v10, v11);
                int ch = c >> 4, off = c & 15;
                int sw = (ch ^ (r0 & 7)) * 16 + off;      // (r0+8)&7 == r0&7
                *reinterpret_cast<uint16_t*>(smem + PF_H + nt * 16384 + r0 * 128 + sw) = h0;
                *reinterpret_cast<uint16_t*>(smem + PF_H + nt * 16384 + (r0 + 8) * 128 + sw) = h1;
            }
        if (nt == 0) __syncthreads();   // H(0) visible; PF_X/PF_W reusable for nt=1
    }

    // single wait + sync: W2 tiles resident, H(1) visible
    cp_wait<0>();
    __syncthreads();

    // ========== GEMM2: Zb = (H @ (16 W2)^T)/16 + b2, two passes, no syncs ===
#pragma unroll 1
    for (int nt2 = 0; nt2 < 2; nt2++) {
        const uint32_t wreg = sbase + (nt2 ? PF_X : PF_W);

        uint32_t acc[2][8][2];
#pragma unroll
        for (int mi = 0; mi < 2; mi++)
#pragma unroll
            for (int nj = 0; nj < 8; nj++) { acc[mi][nj][0] = 0u; acc[mi][nj][1] = 0u; }

#pragma unroll
        for (int s = 0; s < 2; s++) {
            const uint32_t aS = sbase + PF_H + s * 16384;
            const uint32_t bS = wreg + s * 16384;
#pragma unroll
            for (int ks = 0; ks < 4; ks++) {
                uint32_t afr[2][4];
#pragma unroll
                for (int mi = 0; mi < 2; mi++) {
                    int r = wm + mi * 16 + (lane & 15);
                    int c16 = ks * 2 + (lane >> 4);
                    ldm_x4(afr[mi][0], afr[mi][1], afr[mi][2], afr[mi][3],
                           aS + r * 128 + ((c16 ^ (r & 7)) * 16));
                }
                uint32_t bfr[4][4];
#pragma unroll
                for (int bi = 0; bi < 4; bi++) {
                    int r = wn + bi * 16 + (lane & 7) + ((lane >> 4) << 3);
                    int c16 = ks * 2 + ((lane >> 3) & 1);
                    ldm_x4(bfr[bi][0], bfr[bi][1], bfr[bi][2], bfr[bi][3],
                           bS + r * 128 + ((c16 ^ (r & 7)) * 16));
                }
#pragma unroll
                for (int mi = 0; mi < 2; mi++)
#pragma unroll
                    for (int bi = 0; bi < 4; bi++) {
                        mma_e4m3_h(acc[mi][bi * 2 + 0], afr[mi], &bfr[bi][0]);
                        mma_e4m3_h(acc[mi][bi * 2 + 1], afr[mi], &bfr[bi][2]);
                    }
            }
        }

        // epilogue: /16 + bias -> Zb (f16, gmem)
#pragma unroll
        for (int mi = 0; mi < 2; mi++)
#pragma unroll
            for (int nj = 0; nj < 8; nj++) {
                int col = nt2 * 128 + wn + nj * 8 + (lane & 3) * 2;
                float bb0 = __ldg(&b2[col]);
                float bb1 = __ldg(&b2[col + 1]);
                int r0 = bm + wm + mi * 16 + (lane >> 2);
                float2 p0 = __half22float2(*reinterpret_cast<const __half2*>(&acc[mi][nj][0]));
                float2 p1 = __half22float2(*reinterpret_cast<const __half2*>(&acc[mi][nj][1]));
                *reinterpret_cast<__half2*>(Zb + (size_t)r0 * DDIM + col)
                    = __floats2half2_rn(p0.x * 0.0625f + bb0, p0.y * 0.0625f + bb1);
                *reinterpret_cast<__half2*>(Zb + (size_t)(r0 + 8) * DDIM + col)
                    = __floats2half2_rn(p1.x * 0.0625f + bb0, p1.y * 0.0625f + bb1);
            }
    }
}

// ---------------- normalize (from f16) + scaled fp8 concat + diag ------------
__global__ void normdiag_kernel() {
    int n    = blockIdx.x * 8 + (threadIdx.x >> 5);
    int lane = threadIdx.x & 31;
    int b = n >> 12, r = n & 4095;

    uint4 u1 = reinterpret_cast<const uint4*>(g_Zb1 + (size_t)n * DDIM)[lane];
    uint4 u2 = reinterpret_cast<const uint4*>(g_Zb2 + (size_t)n * DDIM)[lane];

    float a[8], c[8];
    {
        float2 t;
        t = __half22float2(*(const __half2*)&u1.x); a[0]=t.x; a[1]=t.y;
        t = __half22float2(*(const __half2*)&u1.y); a[2]=t.x; a[3]=t.y;
        t = __half22float2(*(const __half2*)&u1.z); a[4]=t.x; a[5]=t.y;
        t = __half22float2(*(const __half2*)&u1.w); a[6]=t.x; a[7]=t.y;
        t = __half22float2(*(const __half2*)&u2.x); c[0]=t.x; c[1]=t.y;
        t = __half22float2(*(const __half2*)&u2.y); c[2]=t.x; c[3]=t.y;
        t = __half22float2(*(const __half2*)&u2.z); c[4]=t.x; c[5]=t.y;
        t = __half22float2(*(const __half2*)&u2.w); c[6]=t.x; c[7]=t.y;
    }

    float s1 = 0.f, s2 = 0.f, d = 0.f;
#pragma unroll
    for (int i = 0; i < 8; i++) {
        s1 += a[i] * a[i];
        s2 += c[i] * c[i];
        d  += a[i] * c[i];
    }
#pragma unroll
    for (int off = 16; off >= 1; off >>= 1) {
        s1 += __shfl_xor_sync(0xffffffffu, s1, off);
        s2 += __shfl_xor_sync(0xffffffffu, s2, off);
        d  += __shfl_xor_sync(0xffffffffu, d, off);
    }
    float i1 = ALPHA / fmaxf(sqrtf(s1), 1e-12f);   // fold ALPHA into fp8 values
    float i2 = ALPHA / fmaxf(sqrtf(s2), 1e-12f);

    uint2 q1, q2;
    q1.x = (uint32_t)f2_e4m3x2(a[0]*i1, a[1]*i1) | ((uint32_t)f2_e4m3x2(a[2]*i1, a[3]*i1) << 16);
    q1.y = (uint32_t)f2_e4m3x2(a[4]*i1, a[5]*i1) | ((uint32_t)f2_e4m3x2(a[6]*i1, a[7]*i1) << 16);
    q2.x = (uint32_t)f2_e4m3x2(c[0]*i2, c[1]*i2) | ((uint32_t)f2_e4m3x2(c[2]*i2, c[3]*i2) << 16);
    q2.y = (uint32_t)f2_e4m3x2(c[4]*i2, c[5]*i2) | ((uint32_t)f2_e4m3x2(c[6]*i2, c[7]*i2) << 16);
    reinterpret_cast<uint2*>(g_Zq + ((size_t)b * L2SEQ + r) * DDIM)[lane] = q1;
    reinterpret_cast<uint2*>(g_Zq + ((size_t)b * L2SEQ + LSEQ + r) * DDIM)[lane] = q2;

    if (lane == 0) {
        float nn = fmaxf(sqrtf(s1), 1e-12f) * fmaxf(sqrtf(s2), 1e-12f);
        g_D12[n] = __expf(d / nn * INV_TAU);
        g_Rall[b * L2SEQ + r] = 0.f;
        g_Rall[b * L2SEQ + LSEQ + r] = 0.f;
    }
}

// ---------------- FP8 symmetric Gram (two-stage, f16 acc, packed, occ 3) -----
__global__ __launch_bounds__(256, 3)
void gram_fp8() {
    // decode triangular tile index
    int t = blockIdx.x;
    int i = (int)((2 * NTILE + 1 -
                   sqrtf((float)((2 * NTILE + 1) * (2 * NTILE + 1) - 8 * t))) * 0.5f);
    while ((i + 1) * NTILE - ((i + 1) * i) / 2 <= t) i++;
    while (i * NTILE - (i * (i - 1)) / 2 > t) i--;
    int j = i + (t - (i * NTILE - (i * (i - 1)) / 2));
    const bool do_col = (j != i);
    const int b = blockIdx.y;

    extern __shared__ __align__(128) char smem[];
    const uint32_t sbase = smem_u32(smem);
    const uint32_t sA = sbase;
    const uint32_t sB = sbase + Q_B_OFF;

    const int tid  = threadIdx.x;
    const int wid  = tid >> 5;
    const int lane = tid & 31;

    const uint8_t* Abase = g_Zq + ((size_t)b * L2SEQ + i * 128) * DDIM;
    const uint8_t* Bbase = g_Zq + ((size_t)b * L2SEQ + j * 128) * DDIM;

    const int wm = (wid & 3) * 32;
    const int wn = (wid >> 2) * 64;

    // ---- 2-stage load: stage s covers K bytes [s*128, s*128+128)
#pragma unroll
    for (int s = 0; s < 2; s++) {
#pragma unroll
        for (int it = 0; it < 4; it++) {
            int idx = tid + it * 256;          // 0..1023
            int row = idx >> 3;                // 0..127
            int ch  = idx & 7;                 // 16B chunk in the 128B row
            uint32_t sw = (uint32_t)((ch ^ (row & 7)) * 16);
            cp_async16(sA + s * QSTAGE_BYTES + row * 128 + sw,
                       Abase + (size_t)row * DDIM + s * 128 + ch * 16);
            cp_async16(sB + s * QSTAGE_BYTES + row * 128 + sw,
                       Bbase + (size_t)row * DDIM + s * 128 + ch * 16);
        }
        cp_commit();
    }

    uint32_t acc[2][8][2];
#pragma unroll
    for (int mi = 0; mi < 2; mi++)
#pragma unroll
        for (int nj = 0; nj < 8; nj++) { acc[mi][nj][0] = 0u; acc[mi][nj][1] = 0u; }

#pragma unroll
    for (int s = 0; s < 2; s++) {
        if (s == 0) cp_wait<1>(); else cp_wait<0>();
        __syncthreads();
        const uint32_t aS = sA + s * QSTAGE_BYTES;
        const uint32_t bS = sB + s * QSTAGE_BYTES;
#pragma unroll
        for (int ks = 0; ks < 4; ks++) {       // K=32 bytes each
            uint32_t afr[2][4];
#pragma unroll
            for (int mi = 0; mi < 2; mi++) {
                int r = wm + mi * 16 + (lane & 15);
                int c16 = ks * 2 + (lane >> 4);
                ldm_x4(afr[mi][0], afr[mi][1], afr[mi][2], afr[mi][3],
                       aS + r * 128 + ((c16 ^ (r & 7)) * 16));
            }
            uint32_t bfr[4][4];
#pragma unroll
            for (int bi = 0; bi < 4; bi++) {
                int r = wn + bi * 16 + (lane & 7) + ((lane >> 4) << 3);
                int c16 = ks * 2 + ((lane >> 3) & 1);
                ldm_x4(bfr[bi][0], bfr[bi][1], bfr[bi][2], bfr[bi][3],
                       bS + r * 128 + ((c16 ^ (r & 7)) * 16));
            }
#pragma unroll
            for (int mi = 0; mi < 2; mi++)
#pragma unroll
                for (int bi = 0; bi < 4; bi++) {
                    mma_e4m3_h(acc[mi][bi * 2 + 0], afr[mi], &bfr[bi][0]);
                    mma_e4m3_h(acc[mi][bi * 2 + 1], afr[mi], &bfr[bi][2]);
                }
        }
    }

    // ---- epilogue: packed 2^x; rs AND cs fully packed half2
    float* Rb = g_Rall + b * L2SEQ;
    const int bm = i * 128, bn = j * 128;

    uint32_t rsh0[2] = {0u, 0u};   // [mi]: row r, packed (col c, c+1) partials
    uint32_t rsh1[2] = {0u, 0u};   // [mi]: row r+8
    uint32_t csh[8];
#pragma unroll
    for (int nj = 0; nj < 8; nj++) csh[nj] = 0u;

#pragma unroll
    for (int mi = 0; mi < 2; mi++)
#pragma unroll
        for (int nj = 0; nj < 8; nj++) {
            uint32_t e0 = ex2_h2(acc[mi][nj][0]);   // (row r,   col c | c+1)
            uint32_t e1 = ex2_h2(acc[mi][nj][1]);   // (row r+8, col c | c+1)
            rsh0[mi] = hadd2u(rsh0[mi], e0);
            rsh1[mi] = hadd2u(rsh1[mi], e1);
            csh[nj] = hadd2u(csh[nj], hadd2u(e0, e1));
        }

    // row reduce across the 4 lanes sharing a row (lane bits 0-1), packed
#pragma unroll
    for (int off = 1; off <= 2; off <<= 1)
#pragma unroll
        for (int mi = 0; mi < 2; mi++) {
            rsh0[mi] = hadd2u(rsh0[mi], __shfl_xor_sync(0xffffffffu, rsh0[mi], off));
            rsh1[mi] = hadd2u(rsh1[mi], __shfl_xor_sync(0xffffffffu, rsh1[mi], off));
        }
    if ((lane & 3) == 0) {
#pragma unroll
        for (int mi = 0; mi < 2; mi++) {
            int row = bm + wm + mi * 16 + (lane >> 2);
            float2 v0 = __half22float2(*reinterpret_cast<const __half2*>(&rsh0[mi]));
            float2 v1 = __half22float2(*reinterpret_cast<const __half2*>(&rsh1[mi]));
            atomicAdd(&Rb[row], v0.x + v0.y);
            atomicAdd(&Rb[row + 8], v1.x + v1.y);
        }
    }

    if (do_col) {
#pragma unroll
        for (int off = 4; off <= 16; off <<= 1)
#pragma unroll
            for (int nj = 0; nj < 8; nj++)
                csh[nj] = hadd2u(csh[nj], __shfl_xor_sync(0xffffffffu, csh[nj], off));
        if (lane < 4) {
#pragma unroll
            for (int nj = 0; nj < 8; nj++) {
                float2 cv = __half22float2(*reinterpret_cast<const __half2*>(&csh[nj]));
                int col = bn + wn + nj * 8 + lane * 2;
                atomicAdd(&Rb[col], cv.x);
                atomicAdd(&Rb[col + 1], cv.y);
            }
        }
    }
}

// ---------------- final scalar reduction (2 stages) ---------------------------
__global__ void final1_kernel() {
    __shared__ double sred[256];
    const float E2 = 7.3890560989306495f;   // exp(||z||^2 / tau) = exp(2)
    int n = blockIdx.x * 256 + threadIdx.x;  // 64 blocks x 256 = 16384
    int b = n >> 12, r = n & 4095;
    float d1 = g_Rall[b * L2SEQ + r] - E2;
    float d2 = g_Rall[b * L2SEQ + LSEQ + r] - E2;
    double acc = (double)(logf(d1) + logf(d2) - 2.f * logf(g_D12[n]));
    sred[threadIdx.x] = acc;
    __syncthreads();
    for (int s = 128; s > 0; s >>= 1) {
        if (threadIdx.x < s) sred[threadIdx.x] += sred[threadIdx.x + s];
        __syncthreads();
    }
    if (threadIdx.x == 0) g_partial[blockIdx.x] = sred[0];
}

__global__ void final2_kernel(float* __restrict__ out) {
    __shared__ double sred[64];
    sred[threadIdx.x] = g_partial[threadIdx.x];
    __syncthreads();
    for (int s = 32; s > 0; s >>= 1) {
        if (threadIdx.x < s) sred[threadIdx.x] += sred[threadIdx.x + s];
        __syncthreads();
    }
    if (threadIdx.x == 0) out[0] = (float)(sred[0] / (2.0 * BATCH));
}

// ---------------- launch -------------------------------------------------------
extern "C" void kernel_launch(void* const* d_in, const int* in_sizes, int n_in,
                              void* d_out, int out_size) {
    (void)in_sizes; (void)n_in; (void)out_size;
    const float* X1 = (const float*)d_in[0];
    const float* X2 = (const float*)d_in[1];
    const float* W1 = (const float*)d_in[2];
    const float* b1 = (const float*)d_in[3];
    const float* W2 = (const float*)d_in[4];
    const float* b2 = (const float*)d_in[5];
    float* out = (float*)d_out;

    cudaFuncSetAttribute(proj_fused, cudaFuncAttributeMaxDynamicSharedMemorySize, PF_SMEM_TOTAL);
    cudaFuncSetAttribute(gram_fp8, cudaFuncAttributeMaxDynamicSharedMemorySize, Q_SMEM_TOTAL);

    cvt_all_kernel<<<(CVT_TOTAL + 255) / 256, 256>>>(X1, X2, W1, W2);  // launch 0

    proj_fused<<<dim3(NTOK / 128, 2), 256, PF_SMEM_TOTAL>>>(b1, b2);   // launch 1

    normdiag_kernel<<<NTOK / 8, 256>>>();                              // launch 2

    gram_fp8<<<dim3(NTRI, BATCH), 256, Q_SMEM_TOTAL>>>();              // launch 3

    final1_kernel<<<64, 256>>>();                                      // launch 4
    final2_kernel<<<1, 64>>>(out);                                     // launch 5
}